// round 8
// baseline (speedup 1.0000x reference)
#include <cuda_runtime.h>
#include <cstdint>

// GCN on complete graph + self-loops == per-batch mean pooling -> per-batch
// 4-layer MLP on the mean node feature. TMA-staged weights, 256 threads.
// Dense loops use asm-volatile batched LDS (16 weights + 16 act LDS.128 per
// 16-k block) + __launch_bounds__(256,1) to force ptxas to keep the load
// batch in registers and hide shared-memory latency.

#define ROWS 8
#define NT   256

typedef unsigned long long ull;

// ---- smem layout (floats) ----
#define OFF_OBS   0
#define N_OBS     (ROWS * 512)
#define OFF_P     OFF_OBS
#define OFF_W1    (OFF_OBS + N_OBS)
#define N_W1      (14 * 128)
#define OFF_B1    (OFF_W1 + N_W1)
#define OFF_W2    (OFF_B1 + 128)
#define N_W2      (128 * 128)
#define OFF_B2    (OFF_W2 + N_W2)
#define OFF_WM1   (OFF_B2 + 128)
#define OFF_BM1   (OFF_WM1 + N_W2)
#define OFF_WM2   (OFF_BM1 + 128)
#define N_WM2     (128 * 4)
#define OFF_BM2   (OFF_WM2 + N_WM2)
#define OFF_A     (OFF_BM2 + 4)
#define OFF_B     (OFF_A + ROWS * 128)
#define OFF_F     (OFF_B + ROWS * 128)
#define OFF_MBAR  (OFF_F + ROWS * 16)
#define SMEM_FLOATS (OFF_MBAR + 8)
#define SMEM_BYTES  (SMEM_FLOATS * 4)

#define BYTES_A  ((N_OBS + N_W1 + 128) * 4)
#define BYTES_B0 ((64 * 128) * 4)
#define BYTES_B1 ((64 * 128 + 128) * 4)
#define BYTES_C  ((N_W2 + 128 + N_WM2 + 4) * 4)

__device__ __forceinline__ uint32_t s2u(const void* p) {
    return (uint32_t)__cvta_generic_to_shared(p);
}
__device__ __forceinline__ void mbar_init(uint32_t a, uint32_t cnt) {
    asm volatile("mbarrier.init.shared.b64 [%0], %1;" :: "r"(a), "r"(cnt) : "memory");
}
__device__ __forceinline__ void mbar_expect(uint32_t a, uint32_t bytes) {
    asm volatile("mbarrier.arrive.expect_tx.shared.b64 _, [%0], %1;"
                 :: "r"(a), "r"(bytes) : "memory");
}
__device__ __forceinline__ void bulk_g2s(uint32_t dst, const void* src,
                                         uint32_t bytes, uint32_t mbar) {
    asm volatile("cp.async.bulk.shared::cluster.global.mbarrier::complete_tx::bytes "
                 "[%0], [%1], %2, [%3];"
                 :: "r"(dst), "l"(src), "r"(bytes), "r"(mbar) : "memory");
}
__device__ __forceinline__ void mbar_wait(uint32_t a, uint32_t parity) {
    asm volatile(
        "{\n\t.reg .pred P;\n"
        "WAIT_%=:\n\t"
        "mbarrier.try_wait.parity.shared.b64 P, [%0], %1, 0x989680;\n\t"
        "@P bra.uni DONE_%=;\n\t"
        "bra.uni WAIT_%=;\n"
        "DONE_%=:\n\t}"
        :: "r"(a), "r"(parity) : "memory");
}

// ---- packed f32x2 helpers ----
__device__ __forceinline__ ull pk(float x, float y) {
    ull r;
    asm("mov.b64 %0, {%1, %2};" : "=l"(r) : "f"(x), "f"(y));
    return r;
}
__device__ __forceinline__ void fma2(ull& c, ull a, ull b) {
    asm("fma.rn.f32x2 %0, %1, %2, %3;" : "=l"(c) : "l"(a), "l"(b), "l"(c));
}
__device__ __forceinline__ float2 upk(ull v) {
    float2 r;
    asm("mov.b64 {%0, %1}, %2;" : "=f"(r.x), "=f"(r.y) : "l"(v));
    return r;
}

// Volatile shared loads — cannot be sunk or reordered against each other.
__device__ __forceinline__ float lds_f32(uint32_t addr) {
    float v;
    asm volatile("ld.shared.f32 %0, [%1];" : "=f"(v) : "r"(addr));
    return v;
}
__device__ __forceinline__ void lds_v4(uint32_t addr, ull& lo, ull& hi) {
    asm volatile("ld.shared.v2.b64 {%0, %1}, [%2];" : "=l"(lo), "=l"(hi) : "r"(addr));
}

// One 16-k block: batch-load 16 weights + 16 act vectors (volatile, all in
// flight before use), then 16 pk + 32 FMA2.
// aA/aB: shared addrs of pair A/B activation rows (pair-packed), advanced by
// caller. wAddr: shared addr of W[k0*128 + col].
__device__ __forceinline__ void dense_block16(uint32_t wAddr, uint32_t aA,
                                              uint32_t aB, ull& accA, ull& accB) {
    float w[16];
    #pragma unroll
    for (int i = 0; i < 16; i++) w[i] = lds_f32(wAddr + i * 128 * 4);
    ull a[16], b[16];
    #pragma unroll
    for (int q = 0; q < 4; q++) {
        lds_v4(aA + q * 32,      a[4 * q + 0], a[4 * q + 1]);
        lds_v4(aA + q * 32 + 16, a[4 * q + 2], a[4 * q + 3]);
        lds_v4(aB + q * 32,      b[4 * q + 0], b[4 * q + 1]);
        lds_v4(aB + q * 32 + 16, b[4 * q + 2], b[4 * q + 3]);
    }
    #pragma unroll
    for (int i = 0; i < 16; i++) {
        const ull wp = pk(w[i], w[i]);
        fma2(accA, a[i], wp);
        fma2(accB, b[i], wp);
    }
}

// Full 128-k dense for one h-group: 8 blocks of 16 k.
__device__ __forceinline__ void dense128v(uint32_t sInAddr, uint32_t wColAddr,
                                          ull& accA, ull& accB, int h) {
    const uint32_t aA = sInAddr + (2 * h) * 256 * 4;
    const uint32_t aB = sInAddr + (2 * h + 1) * 256 * 4;
    #pragma unroll
    for (int blk = 0; blk < 8; blk++) {
        dense_block16(wColAddr + blk * 16 * 128 * 4,
                      aA + blk * 16 * 2 * 4, aB + blk * 16 * 2 * 4, accA, accB);
    }
}

__global__ __launch_bounds__(NT, 1) void gcnn_actor_kernel(
    const float* __restrict__ obs,
    const float* __restrict__ W1,  const float* __restrict__ b1,
    const float* __restrict__ W2,  const float* __restrict__ b2,
    const float* __restrict__ Wm1, const float* __restrict__ bm1,
    const float* __restrict__ Wm2, const float* __restrict__ bm2,
    float* __restrict__ out, int std_off)
{
    extern __shared__ float sm[];
    float* sObs = sm + OFF_OBS;
    float* sP   = sm + OFF_P;
    float* sA   = sm + OFF_A;
    float* sB   = sm + OFF_B;
    float* sF   = sm + OFF_F;

    const int tid  = threadIdx.x;
    const int col  = tid & 127;
    const int h    = tid >> 7;
    const int base = blockIdx.x * ROWS;

    const uint32_t smBase = s2u(sm);
    const uint32_t mbarA  = smBase + OFF_MBAR * 4;
    const uint32_t mbarB0 = mbarA + 8;
    const uint32_t mbarB1 = mbarA + 16;
    const uint32_t mbarC  = mbarA + 24;

    if (tid == 0) {
        mbar_init(mbarA, 1); mbar_init(mbarB0, 1);
        mbar_init(mbarB1, 1); mbar_init(mbarC, 1);
    }
    __syncthreads();

    if (tid == 0) {
        mbar_expect(mbarA, BYTES_A);
        bulk_g2s(smBase + OFF_OBS * 4, obs + (size_t)base * 512, N_OBS * 4, mbarA);
        bulk_g2s(smBase + OFF_W1 * 4,  W1,  N_W1 * 4,  mbarA);
        bulk_g2s(smBase + OFF_B1 * 4,  b1,  128 * 4,   mbarA);
        mbar_expect(mbarB0, BYTES_B0);
        bulk_g2s(smBase + OFF_W2 * 4,  W2,  64 * 128 * 4, mbarB0);
        mbar_expect(mbarB1, BYTES_B1);
        bulk_g2s(smBase + (OFF_W2 + 64 * 128) * 4, W2 + 64 * 128, 64 * 128 * 4, mbarB1);
        bulk_g2s(smBase + OFF_B2 * 4,  b2,  128 * 4,   mbarB1);
        mbar_expect(mbarC, BYTES_C);
        bulk_g2s(smBase + OFF_WM1 * 4, Wm1, N_W2 * 4,  mbarC);
        bulk_g2s(smBase + OFF_BM1 * 4, bm1, 128 * 4,   mbarC);
        bulk_g2s(smBase + OFF_WM2 * 4, Wm2, N_WM2 * 4, mbarC);
        bulk_g2s(smBase + OFF_BM2 * 4, bm2, 4 * 4,     mbarC);
    }

    mbar_wait(mbarA, 0);

    // fbar: 128 threads, (r = tid>>4, d = tid&15), feature dims 2..15
    if (tid < 128) {
        const int r = tid >> 4, d = tid & 15;
        if (d < 14) {
            float s = 0.f;
            #pragma unroll
            for (int n = 0; n < 32; n++) s += sObs[r * 512 + n * 16 + 2 + d];
            sF[r * 16 + d] = s * (1.0f / 32.0f);
        }
    }
    __syncthreads();

    // h1 = relu(fbar @ W1 + b1) -> sA (pair-packed); thread does rows 4h..4h+3
    {
        float w[14];
        #pragma unroll
        for (int d = 0; d < 14; d++) w[d] = sm[OFF_W1 + d * 128 + col];
        const float bb = sm[OFF_B1 + col];
        float acc[4];
        #pragma unroll
        for (int q = 0; q < 4; q++) {
            const int r = 4 * h + q;
            float a = bb;
            #pragma unroll
            for (int d = 0; d < 14; d++) a = fmaf(sF[r * 16 + d], w[d], a);
            acc[q] = fmaxf(a, 0.f);
        }
        reinterpret_cast<float2*>(sA)[(2 * h) * 128 + col]     = make_float2(acc[0], acc[1]);
        reinterpret_cast<float2*>(sA)[(2 * h + 1) * 128 + col] = make_float2(acc[2], acc[3]);
    }
    asm volatile("bar.sync %0, 128;" :: "r"(1 + h) : "memory");

    const uint32_t sAaddr = smBase + OFF_A * 4;
    const uint32_t sBaddr = smBase + OFF_B * 4;

    // ---- layer 2: h2 = relu(h1 @ W2 + b2), W2 in two TMA chunks ----
    {
        ull accA = 0ULL, accB = 0ULL;
        const uint32_t wA = smBase + (OFF_W2 + col) * 4;
        const uint32_t aA = sAaddr + (2 * h) * 256 * 4;
        const uint32_t aB = sAaddr + (2 * h + 1) * 256 * 4;
        mbar_wait(mbarB0, 0);
        #pragma unroll
        for (int blk = 0; blk < 4; blk++)
            dense_block16(wA + blk * 16 * 128 * 4,
                          aA + blk * 128, aB + blk * 128, accA, accB);
        mbar_wait(mbarB1, 0);
        #pragma unroll
        for (int blk = 4; blk < 8; blk++)
            dense_block16(wA + blk * 16 * 128 * 4,
                          aA + blk * 128, aB + blk * 128, accA, accB);
        const float bb = sm[OFF_B2 + col];
        const float2 vA = upk(accA), vB = upk(accB);
        reinterpret_cast<float2*>(sB)[(2 * h) * 128 + col] =
            make_float2(fmaxf(vA.x + bb, 0.f), fmaxf(vA.y + bb, 0.f));
        reinterpret_cast<float2*>(sB)[(2 * h + 1) * 128 + col] =
            make_float2(fmaxf(vB.x + bb, 0.f), fmaxf(vB.y + bb, 0.f));
    }
    asm volatile("bar.sync %0, 128;" :: "r"(1 + h) : "memory");

    // ---- layer 3: m = relu(h2 @ Wm1 + bm1) ----
    {
        ull accA = 0ULL, accB = 0ULL;
        mbar_wait(mbarC, 0);
        dense128v(sBaddr, smBase + (OFF_WM1 + col) * 4, accA, accB, h);
        const float bb = sm[OFF_BM1 + col];
        const float2 vA = upk(accA), vB = upk(accB);
        reinterpret_cast<float2*>(sA)[(2 * h) * 128 + col] =
            make_float2(fmaxf(vA.x + bb, 0.f), fmaxf(vA.y + bb, 0.f));
        reinterpret_cast<float2*>(sA)[(2 * h + 1) * 128 + col] =
            make_float2(fmaxf(vB.x + bb, 0.f), fmaxf(vB.y + bb, 0.f));
    }
    __syncthreads();

    // ---- o = m @ Wm2 + bm2 : 256 threads = 8 rows x 4 cols x 8 k-slices ----
    {
        const int r = tid >> 5, c = (tid >> 3) & 3, s = tid & 7;
        const int pair = r >> 1, e = r & 1;
        float p = 0.f;
        #pragma unroll
        for (int i = 0; i < 16; i++) {
            const int k = s * 16 + i;
            p = fmaf(sA[pair * 256 + 2 * k + e], sm[OFF_WM2 + k * 4 + c], p);
        }
        sP[tid] = p;
    }
    __syncthreads();
    if (tid < ROWS * 4) {
        const int r = tid >> 2, c = tid & 3;
        float o = sm[OFF_BM2 + c];
        #pragma unroll
        for (int s = 0; s < 8; s++) o += sP[(r << 5) | (c << 3) | s];
        if (c < 2) {
            sF[r * 16 + c] = o;
        } else {
            const float t = tanhf(o);
            sF[r * 16 + 8 + (c - 2)] = __expf(-5.0f + 3.5f * (t + 1.0f));
        }
    }
    __syncthreads();

    // ---- write: one float4 per thread, fully coalesced ----
    {
        const int plane = tid >> 7;
        const int r = (tid & 127) >> 4;
        const int i = tid & 15;
        const int off = plane ? 8 : 0;
        const float v0 = sF[r * 16 + off + 0];
        const float v1 = sF[r * 16 + off + 1];
        float* dst = out + (plane ? (size_t)std_off : 0) + (size_t)(base + r) * 64;
        reinterpret_cast<float4*>(dst)[i] = make_float4(v0, v1, v0, v1);
    }
}

extern "C" void kernel_launch(void* const* d_in, const int* in_sizes, int n_in,
                              void* d_out, int out_size) {
    const float* obs = (const float*)d_in[0];
    const float* W1  = (const float*)d_in[1];
    const float* b1  = (const float*)d_in[2];
    const float* W2  = (const float*)d_in[3];
    const float* b2  = (const float*)d_in[4];
    const float* Wm1 = (const float*)d_in[5];
    const float* bm1 = (const float*)d_in[6];
    const float* Wm2 = (const float*)d_in[7];
    const float* bm2 = (const float*)d_in[8];
    float* out = (float*)d_out;

    const int bs = in_sizes[0] / 512;
    const int std_off = bs * 64;
    const int grid = bs / ROWS;

    cudaFuncSetAttribute(gcnn_actor_kernel,
                         cudaFuncAttributeMaxDynamicSharedMemorySize, SMEM_BYTES);
    gcnn_actor_kernel<<<grid, NT, SMEM_BYTES>>>(obs, W1, b1, W2, b2, Wm1, bm1,
                                                Wm2, bm2, out, std_off);
}

// round 9
// speedup vs baseline: 1.0239x; 1.0239x over previous
#include <cuda_runtime.h>
#include <cstdint>

// GCN on complete graph + self-loops == per-batch mean pooling -> per-batch
// 4-layer MLP on the mean node feature.
// Key change this round: 2 independent CTAs per SM (grid=256, ROWS=4,
// NT=128, ~87KB smem each) so one CTA's TMA/barrier bubbles overlap the
// other CTA's compute. W2 and Wm1 share a single reused 64KB smem buffer.

#define ROWS 4
#define NT   128

typedef unsigned long long ull;

// ---- smem layout (floats) ----
#define OFF_OBS   0
#define N_OBS     (ROWS * 512)              // 2048
#define OFF_P     OFF_OBS                    // tail scratch (obs dead by then)
#define OFF_W1    (OFF_OBS + N_OBS)          // 2048
#define N_W1      (14 * 128)                 // 1792
#define OFF_B1    (OFF_W1 + N_W1)            // 3840
#define OFF_WM2   (OFF_B1 + 128)             // 3968
#define N_WM2     (128 * 4)                  // 512
#define OFF_BM2   (OFF_WM2 + N_WM2)          // 4480
#define OFF_B2    (OFF_BM2 + 4)              // 4484
#define OFF_BM1   (OFF_B2 + 128)             // 4612
#define OFF_A     (OFF_BM1 + 128)            // 4740 (*4 = 18960, 16B aligned)
#define OFF_Bb    (OFF_A + ROWS * 128)       // 5252
#define OFF_F     (OFF_Bb + ROWS * 128)      // 5764 (fbar + results)
#define OFF_MBAR  (OFF_F + ROWS * 16)        // 5828 (*4 = 23312, 8B aligned)
#define OFF_WBUF  5856                       // *4 = 23424, 128B aligned
#define N_WBUF    (128 * 128)                // 16384 floats (64KB), W2 then Wm1
#define SMEM_FLOATS (OFF_WBUF + N_WBUF)      // 22240
#define SMEM_BYTES  (SMEM_FLOATS * 4)        // 88960 (~87KB) -> 2 CTAs/SM

#define BYTES_A ((N_OBS + N_W1 + 128 + N_WMX) * 4)
#define N_WMX   (N_WM2 + 4 + 128 + 128)      // Wm2+bm2+b2+bm1
#define BYTES_W (128 * 128 * 4)              // one weight matrix

__device__ __forceinline__ uint32_t s2u(const void* p) {
    return (uint32_t)__cvta_generic_to_shared(p);
}
__device__ __forceinline__ void mbar_init(uint32_t a, uint32_t cnt) {
    asm volatile("mbarrier.init.shared.b64 [%0], %1;" :: "r"(a), "r"(cnt) : "memory");
}
__device__ __forceinline__ void mbar_expect(uint32_t a, uint32_t bytes) {
    asm volatile("mbarrier.arrive.expect_tx.shared.b64 _, [%0], %1;"
                 :: "r"(a), "r"(bytes) : "memory");
}
__device__ __forceinline__ void bulk_g2s(uint32_t dst, const void* src,
                                         uint32_t bytes, uint32_t mbar) {
    asm volatile("cp.async.bulk.shared::cluster.global.mbarrier::complete_tx::bytes "
                 "[%0], [%1], %2, [%3];"
                 :: "r"(dst), "l"(src), "r"(bytes), "r"(mbar) : "memory");
}
__device__ __forceinline__ void mbar_wait(uint32_t a, uint32_t parity) {
    asm volatile(
        "{\n\t.reg .pred P;\n"
        "WAIT_%=:\n\t"
        "mbarrier.try_wait.parity.shared.b64 P, [%0], %1, 0x989680;\n\t"
        "@P bra.uni DONE_%=;\n\t"
        "bra.uni WAIT_%=;\n"
        "DONE_%=:\n\t}"
        :: "r"(a), "r"(parity) : "memory");
}

// ---- packed f32x2 helpers ----
__device__ __forceinline__ ull pk(float x, float y) {
    ull r;
    asm("mov.b64 %0, {%1, %2};" : "=l"(r) : "f"(x), "f"(y));
    return r;
}
__device__ __forceinline__ void fma2(ull& c, ull a, ull b) {
    asm("fma.rn.f32x2 %0, %1, %2, %3;" : "=l"(c) : "l"(a), "l"(b), "l"(c));
}
__device__ __forceinline__ float2 upk(ull v) {
    float2 r;
    asm("mov.b64 {%0, %1}, %2;" : "=f"(r.x), "=f"(r.y) : "l"(v));
    return r;
}
__device__ __forceinline__ float lds_f32(uint32_t addr) {
    float v;
    asm volatile("ld.shared.f32 %0, [%1];" : "=f"(v) : "r"(addr));
    return v;
}
__device__ __forceinline__ void lds_v4(uint32_t addr, ull& lo, ull& hi) {
    asm volatile("ld.shared.v2.b64 {%0, %1}, [%2];" : "=l"(lo), "=l"(hi) : "r"(addr));
}

// One 16-k block: batch 16 weight LDS + 8 act LDS.128 (both pairs), then FMAs.
__device__ __forceinline__ void dense_block16(uint32_t wAddr, uint32_t aA,
                                              uint32_t aB, ull& accA, ull& accB) {
    float w[16];
    #pragma unroll
    for (int i = 0; i < 16; i++) w[i] = lds_f32(wAddr + i * 128 * 4);
    ull a[16], b[16];
    #pragma unroll
    for (int q = 0; q < 4; q++) {
        lds_v4(aA + q * 32,      a[4 * q + 0], a[4 * q + 1]);
        lds_v4(aA + q * 32 + 16, a[4 * q + 2], a[4 * q + 3]);
        lds_v4(aB + q * 32,      b[4 * q + 0], b[4 * q + 1]);
        lds_v4(aB + q * 32 + 16, b[4 * q + 2], b[4 * q + 3]);
    }
    #pragma unroll
    for (int i = 0; i < 16; i++) {
        const ull wp = pk(w[i], w[i]);
        fma2(accA, a[i], wp);
        fma2(accB, b[i], wp);
    }
}

__global__ __launch_bounds__(NT, 2) void gcnn_actor_kernel(
    const float* __restrict__ obs,
    const float* __restrict__ W1,  const float* __restrict__ b1,
    const float* __restrict__ W2,  const float* __restrict__ b2,
    const float* __restrict__ Wm1, const float* __restrict__ bm1,
    const float* __restrict__ Wm2, const float* __restrict__ bm2,
    float* __restrict__ out, int std_off)
{
    extern __shared__ float sm[];
    float* sObs = sm + OFF_OBS;
    float* sP   = sm + OFF_P;
    float* sA   = sm + OFF_A;
    float* sBb  = sm + OFF_Bb;
    float* sF   = sm + OFF_F;

    const int tid  = threadIdx.x;
    const int col  = tid;                 // 0..127
    const int base = blockIdx.x * ROWS;

    const uint32_t smBase = s2u(sm);
    const uint32_t mbarA  = smBase + OFF_MBAR * 4;
    const uint32_t mbarB  = mbarA + 8;
    const uint32_t mbarC  = mbarA + 16;
    const uint32_t wbuf   = smBase + OFF_WBUF * 4;

    if (tid == 0) { mbar_init(mbarA, 1); mbar_init(mbarB, 1); mbar_init(mbarC, 1); }
    __syncthreads();

    if (tid == 0) {
        mbar_expect(mbarA, BYTES_A);
        bulk_g2s(smBase + OFF_OBS * 4, obs + (size_t)base * 512, N_OBS * 4, mbarA);
        bulk_g2s(smBase + OFF_W1 * 4,  W1,  N_W1 * 4,  mbarA);
        bulk_g2s(smBase + OFF_B1 * 4,  b1,  128 * 4,   mbarA);
        bulk_g2s(smBase + OFF_WM2 * 4, Wm2, N_WM2 * 4, mbarA);
        bulk_g2s(smBase + OFF_BM2 * 4, bm2, 4 * 4,     mbarA);
        bulk_g2s(smBase + OFF_B2 * 4,  b2,  128 * 4,   mbarA);
        bulk_g2s(smBase + OFF_BM1 * 4, bm1, 128 * 4,   mbarA);
        mbar_expect(mbarB, BYTES_W);
        bulk_g2s(wbuf, W2, BYTES_W, mbarB);
    }

    mbar_wait(mbarA, 0);

    // fbar: 64 threads, (r = tid>>4, d = tid&15), feature dims 2..15
    if (tid < 64) {
        const int r = tid >> 4, d = tid & 15;
        if (d < 14) {
            float s = 0.f;
            #pragma unroll
            for (int n = 0; n < 32; n++) s += sObs[r * 512 + n * 16 + 2 + d];
            sF[r * 16 + d] = s * (1.0f / 32.0f);
        }
    }
    __syncthreads();

    // h1 = relu(fbar @ W1 + b1) -> sA (pair-packed, 2 pairs = 4 rows)
    {
        float w[14];
        #pragma unroll
        for (int d = 0; d < 14; d++) w[d] = sm[OFF_W1 + d * 128 + col];
        const float bb = sm[OFF_B1 + col];
        float acc[4];
        #pragma unroll
        for (int r = 0; r < 4; r++) {
            float a = bb;
            #pragma unroll
            for (int d = 0; d < 14; d++) a = fmaf(sF[r * 16 + d], w[d], a);
            acc[r] = fmaxf(a, 0.f);
        }
        reinterpret_cast<float2*>(sA)[0 * 128 + col] = make_float2(acc[0], acc[1]);
        reinterpret_cast<float2*>(sA)[1 * 128 + col] = make_float2(acc[2], acc[3]);
    }
    __syncthreads();

    const uint32_t sAaddr = smBase + OFF_A * 4;
    const uint32_t sBaddr = smBase + OFF_Bb * 4;
    const uint32_t wCol   = wbuf + col * 4;

    // ---- layer 2: h2 = relu(h1 @ W2 + b2), W2 in WBUF ----
    {
        ull accA = 0ULL, accB = 0ULL;
        mbar_wait(mbarB, 0);
        #pragma unroll
        for (int blk = 0; blk < 8; blk++)
            dense_block16(wCol + blk * 16 * 128 * 4,
                          sAaddr + blk * 128,
                          sAaddr + 256 * 4 + blk * 128, accA, accB);
        const float bb = sm[OFF_B2 + col];
        const float2 vA = upk(accA), vB = upk(accB);
        reinterpret_cast<float2*>(sBb)[0 * 128 + col] =
            make_float2(fmaxf(vA.x + bb, 0.f), fmaxf(vA.y + bb, 0.f));
        reinterpret_cast<float2*>(sBb)[1 * 128 + col] =
            make_float2(fmaxf(vB.x + bb, 0.f), fmaxf(vB.y + bb, 0.f));
    }
    __syncthreads();   // all reads of W2 done (results stored) -> safe to overwrite

    if (tid == 0) {
        mbar_expect(mbarC, BYTES_W);
        bulk_g2s(wbuf, Wm1, BYTES_W, mbarC);
    }

    // ---- layer 3: m = relu(h2 @ Wm1 + bm1), Wm1 reuses WBUF ----
    {
        ull accA = 0ULL, accB = 0ULL;
        mbar_wait(mbarC, 0);
        #pragma unroll
        for (int blk = 0; blk < 8; blk++)
            dense_block16(wCol + blk * 16 * 128 * 4,
                          sBaddr + blk * 128,
                          sBaddr + 256 * 4 + blk * 128, accA, accB);
        const float bb = sm[OFF_BM1 + col];
        const float2 vA = upk(accA), vB = upk(accB);
        reinterpret_cast<float2*>(sA)[0 * 128 + col] =
            make_float2(fmaxf(vA.x + bb, 0.f), fmaxf(vA.y + bb, 0.f));
        reinterpret_cast<float2*>(sA)[1 * 128 + col] =
            make_float2(fmaxf(vB.x + bb, 0.f), fmaxf(vB.y + bb, 0.f));
    }
    __syncthreads();

    // ---- o = m @ Wm2 + bm2 : 128 threads = 4 rows x 4 cols x 8 k-slices ----
    {
        const int r = tid >> 5, c = (tid >> 3) & 3, s = tid & 7;
        const int pair = r >> 1, e = r & 1;
        float p = 0.f;
        #pragma unroll
        for (int i = 0; i < 16; i++) {
            const int k = s * 16 + i;
            p = fmaf(sA[pair * 256 + 2 * k + e], sm[OFF_WM2 + k * 4 + c], p);
        }
        sP[tid] = p;
    }
    __syncthreads();
    if (tid < ROWS * 4) {
        const int r = tid >> 2, c = tid & 3;
        float o = sm[OFF_BM2 + c];
        #pragma unroll
        for (int s = 0; s < 8; s++) o += sP[(r << 5) | (c << 3) | s];
        if (c < 2) {
            sF[r * 16 + c] = o;                                   // mu
        } else {
            const float t = tanhf(o);
            sF[r * 16 + 8 + (c - 2)] = __expf(-5.0f + 3.5f * (t + 1.0f)); // std
        }
    }
    __syncthreads();

    // ---- write: one float4 per thread (2 planes x 4 rows x 16), coalesced ----
    {
        const int plane = tid >> 6;           // 0 = mu, 1 = std
        const int r = (tid >> 4) & 3;         // 0..3
        const int i = tid & 15;               // 0..15
        const int off = plane ? 8 : 0;
        const float v0 = sF[r * 16 + off + 0];
        const float v1 = sF[r * 16 + off + 1];
        float* dst = out + (plane ? (size_t)std_off : 0) + (size_t)(base + r) * 64;
        reinterpret_cast<float4*>(dst)[i] = make_float4(v0, v1, v0, v1);
    }
}

extern "C" void kernel_launch(void* const* d_in, const int* in_sizes, int n_in,
                              void* d_out, int out_size) {
    const float* obs = (const float*)d_in[0];
    const float* W1  = (const float*)d_in[1];
    const float* b1  = (const float*)d_in[2];
    const float* W2  = (const float*)d_in[3];
    const float* b2  = (const float*)d_in[4];
    const float* Wm1 = (const float*)d_in[5];
    const float* bm1 = (const float*)d_in[6];
    const float* Wm2 = (const float*)d_in[7];
    const float* bm2 = (const float*)d_in[8];
    float* out = (float*)d_out;

    const int bs = in_sizes[0] / 512;
    const int std_off = bs * 64;
    const int grid = bs / ROWS;            // 256 CTAs -> 2 per SM

    cudaFuncSetAttribute(gcnn_actor_kernel,
                         cudaFuncAttributeMaxDynamicSharedMemorySize, SMEM_BYTES);
    gcnn_actor_kernel<<<grid, NT, SMEM_BYTES>>>(obs, W1, b1, W2, b2, Wm1, bm1,
                                                Wm2, bm2, out, std_off);
}